// round 1
// baseline (speedup 1.0000x reference)
#include <cuda_runtime.h>

#define TPB 256

namespace {
constexpr int B  = 32;
constexpr int C  = 64;
constexpr int H  = 112;
constexpr int W  = 112;
constexpr int F  = 128;
constexpr int CC = 8;    // channels per K-chunk
constexpr int TY = 8;    // output rows per block
constexpr int TX = 16;   // output cols per block
}

// Block: one batch, TY x TX output pixels, all F filters.
// Thread: 8 filters x 8 x-contiguous pixels (64 fp32 accumulators).
__global__ __launch_bounds__(TPB, 2)
void conv3x3_kernel(const float* __restrict__ in,
                    const float* __restrict__ wt,
                    float* __restrict__ out)
{
    __shared__ float s_in[CC][TY + 2][TX + 2];   // 8*10*18*4 = 5.76 KB
    __shared__ float s_w[CC * 9][F];             // 72*128*4  = 36.9 KB (swizzled)

    const int bx = blockIdx.x * TX;
    const int by = blockIdx.y * TY;
    const int bb = blockIdx.z;

    const int tid = threadIdx.x;
    const int fg  = tid & 15;          // filter group 0..15
    const int pg  = tid >> 4;          // pixel group 0..15
    const int r   = pg >> 1;           // tile row 0..7
    const int xg  = (pg & 1) << 3;     // tile x offset 0 or 8
    const int f0  = fg << 3;           // first filter of this thread

    float acc[8][8];
#pragma unroll
    for (int i = 0; i < 8; ++i)
#pragma unroll
        for (int j = 0; j < 8; ++j) acc[i][j] = 0.f;

    const float* in_b = in + (size_t)bb * C * H * W;

#pragma unroll 1
    for (int cc0 = 0; cc0 < C; cc0 += CC) {
        __syncthreads();

        // ---- stage input halo tile: CC x (TY+2) x (TX+2) = 1440 floats ----
        for (int i = tid; i < CC * (TY + 2) * (TX + 2); i += TPB) {
            int x  = i % (TX + 2);
            int t  = i / (TX + 2);
            int y  = t % (TY + 2);
            int c  = t / (TY + 2);
            int gx = bx + x - 1;
            int gy = by + y - 1;
            float v = 0.f;
            if ((unsigned)gx < (unsigned)W && (unsigned)gy < (unsigned)H)
                v = in_b[((cc0 + c) * H + gy) * W + gx];
            s_in[c][y][x] = v;
        }

        // ---- stage weight chunk: F filters x 72 contiguous floats each ----
        // Global layout per filter: wt[f*576 + cc0*9 + j], j in [0,72).
        // Coalesced float4 loads along j; swizzled scatter into s_w[j][f'].
        {
            const float4* wp = (const float4*)(wt + cc0 * 9);  // 16B aligned: cc0*9 % 4 == 0
#pragma unroll
            for (int k = 0; k < 9; ++k) {      // 2304 float4 / 256 threads = 9
                int idx = tid + k * TPB;
                int f = idx / 18;              // filter
                int g = idx % 18;              // float4 index within 72-run
                float4 v = wp[f * 144 + g];
                int fsw = f ^ ((g & 3) << 3);  // XOR swizzle: spreads STS banks
                s_w[g * 4 + 0][fsw] = v.x;
                s_w[g * 4 + 1][fsw] = v.y;
                s_w[g * 4 + 2][fsw] = v.z;
                s_w[g * 4 + 3][fsw] = v.w;
            }
        }
        __syncthreads();

        // ---- compute: per channel, per dy: load 10-wide input row once,
        //      reuse across 3 taps (dx). 192 FFMA per (c,dy). ----
#pragma unroll 1
        for (int c = 0; c < CC; ++c) {
#pragma unroll
            for (int dy = 0; dy < 3; ++dy) {
                float xin[10];
#pragma unroll
                for (int i = 0; i < 10; ++i)
                    xin[i] = s_in[c][r + dy][xg + i];
#pragma unroll
                for (int dx = 0; dx < 3; ++dx) {
                    const int j  = c * 9 + dy * 3 + dx;
                    const int fb = f0 ^ (((j >> 2) & 3) << 3);  // undo swizzle
                    const float4 wa = *(const float4*)&s_w[j][fb];
                    const float4 wb = *(const float4*)&s_w[j][fb + 4];
                    const float wv[8] = {wa.x, wa.y, wa.z, wa.w,
                                         wb.x, wb.y, wb.z, wb.w};
#pragma unroll
                    for (int ff = 0; ff < 8; ++ff)
#pragma unroll
                        for (int p = 0; p < 8; ++p)
                            acc[ff][p] = fmaf(wv[ff], xin[p + dx], acc[ff][p]);
                }
            }
        }
    }

    // ---- write output: 8 filter rows x 8 x-contiguous floats (2x STG.128) ----
    const int y  = by + r;
    const int x0 = bx + xg;
    float* op = out + (((size_t)bb * F + f0) * H + y) * W + x0;
#pragma unroll
    for (int ff = 0; ff < 8; ++ff) {
        float4 v0 = make_float4(acc[ff][0], acc[ff][1], acc[ff][2], acc[ff][3]);
        float4 v1 = make_float4(acc[ff][4], acc[ff][5], acc[ff][6], acc[ff][7]);
        *(float4*)(op + 0) = v0;
        *(float4*)(op + 4) = v1;
        op += (size_t)H * W;
    }
}

extern "C" void kernel_launch(void* const* d_in, const int* in_sizes, int n_in,
                              void* d_out, int out_size)
{
    (void)in_sizes; (void)n_in; (void)out_size;
    const float* in = (const float*)d_in[0];   // dataset [32,64,112,112] f32
    const float* wt = (const float*)d_in[1];   // filters [128,64,3,3]    f32
    float* out = (float*)d_out;                // [32,128,112,112] f32

    dim3 grid(W / TX, H / TY, B);              // (7, 14, 32) = 3136 blocks
    conv3x3_kernel<<<grid, TPB>>>(in, wt, out);
}

// round 2
// speedup vs baseline: 1.1801x; 1.1801x over previous
#include <cuda_runtime.h>

#define TPB 256

namespace {
constexpr int B  = 32;
constexpr int C  = 64;
constexpr int H  = 112;
constexpr int W  = 112;
constexpr int F  = 128;
constexpr int CC = 8;    // channels per K-chunk
constexpr int TY = 8;    // output rows per block
constexpr int TX = 16;   // output cols per block
}

// Packed fp32x2 FMA (Blackwell): d.lo += a.lo*b.lo; d.hi += a.hi*b.hi (full fp32)
__device__ __forceinline__ void fma2(unsigned long long& d,
                                     unsigned long long a,
                                     unsigned long long b) {
    asm("fma.rn.f32x2 %0, %1, %2, %0;" : "+l"(d) : "l"(a), "l"(b));
}
// Broadcast one float into both halves of a 64-bit f32x2 register
__device__ __forceinline__ unsigned long long bcast2(float x) {
    unsigned long long r;
    asm("mov.b64 %0, {%1, %1};" : "=l"(r) : "f"(x));
    return r;
}
__device__ __forceinline__ void unpack2(unsigned long long v, float& lo, float& hi) {
    asm("mov.b64 {%0, %1}, %2;" : "=f"(lo), "=f"(hi) : "l"(v));
}

// Block: one batch, TY x TX output pixels, all F filters.
// Thread: 8 filters x 8 x-contiguous pixels; accumulators packed in f32x2
// pairs along the FILTER axis (adjacent filters share a 64-bit register).
__global__ __launch_bounds__(TPB, 2)
void conv3x3_kernel(const float* __restrict__ in,
                    const float* __restrict__ wt,
                    float* __restrict__ out)
{
    __shared__ float s_in[CC][TY + 2][TX + 2];   // 5.76 KB
    __shared__ float s_w[CC * 9][F];             // 36.9 KB (bank-swizzled)

    const int bx = blockIdx.x * TX;
    const int by = blockIdx.y * TY;
    const int bb = blockIdx.z;

    const int tid = threadIdx.x;
    const int fg  = tid & 15;          // filter group 0..15
    const int pg  = tid >> 4;          // pixel group 0..15
    const int r   = pg >> 1;           // tile row 0..7
    const int xg  = (pg & 1) << 3;     // tile x offset 0 or 8
    const int f0  = fg << 3;           // first filter of this thread

    // acc2[q][p] = (out[f0+2q][p], out[f0+2q+1][p]) packed f32x2
    unsigned long long acc2[4][8];
#pragma unroll
    for (int q = 0; q < 4; ++q)
#pragma unroll
        for (int p = 0; p < 8; ++p) acc2[q][p] = 0ull;

    const float* in_b = in + (size_t)bb * C * H * W;

#pragma unroll 1
    for (int cc0 = 0; cc0 < C; cc0 += CC) {
        __syncthreads();

        // ---- stage input halo tile: CC x (TY+2) x (TX+2) = 1440 floats ----
        for (int i = tid; i < CC * (TY + 2) * (TX + 2); i += TPB) {
            int x  = i % (TX + 2);
            int t  = i / (TX + 2);
            int y  = t % (TY + 2);
            int c  = t / (TY + 2);
            int gx = bx + x - 1;
            int gy = by + y - 1;
            float v = 0.f;
            if ((unsigned)gx < (unsigned)W && (unsigned)gy < (unsigned)H)
                v = in_b[((cc0 + c) * H + gy) * W + gx];
            s_in[c][y][x] = v;
        }

        // ---- stage weight chunk: F filters x 72 contiguous floats each ----
        {
            const float4* wp = (const float4*)(wt + cc0 * 9);  // 16B aligned
#pragma unroll
            for (int k = 0; k < 9; ++k) {      // 2304 float4 / 256 threads
                int idx = tid + k * TPB;
                int f = idx / 18;              // filter
                int g = idx % 18;              // float4 index within 72-run
                float4 v = wp[f * 144 + g];
                int fsw = f ^ ((g & 3) << 3);  // XOR swizzle (8-filter granule)
                s_w[g * 4 + 0][fsw] = v.x;
                s_w[g * 4 + 1][fsw] = v.y;
                s_w[g * 4 + 2][fsw] = v.z;
                s_w[g * 4 + 3][fsw] = v.w;
            }
        }
        __syncthreads();

        // ---- compute: per (c,dy) broadcast 10 input values into f32x2,
        //      then 96 FFMA2 across 3 taps x 4 filter-pairs x 8 pixels ----
#pragma unroll 1
        for (int c = 0; c < CC; ++c) {
#pragma unroll
            for (int dy = 0; dy < 3; ++dy) {
                unsigned long long xin2[10];
#pragma unroll
                for (int i = 0; i < 10; ++i)
                    xin2[i] = bcast2(s_in[c][r + dy][xg + i]);
#pragma unroll
                for (int dx = 0; dx < 3; ++dx) {
                    const int j  = c * 9 + dy * 3 + dx;
                    const int fb = f0 ^ (((j >> 2) & 3) << 3);  // undo swizzle
                    // 16B loads; adjacent filters are natively packed pairs
                    const ulonglong2 wlo = *(const ulonglong2*)&s_w[j][fb];
                    const ulonglong2 whi = *(const ulonglong2*)&s_w[j][fb + 4];
                    const unsigned long long w2[4] = {wlo.x, wlo.y, whi.x, whi.y};
#pragma unroll
                    for (int q = 0; q < 4; ++q)
#pragma unroll
                        for (int p = 0; p < 8; ++p)
                            fma2(acc2[q][p], w2[q], xin2[p + dx]);
                }
            }
        }
    }

    // ---- epilogue: unpack filter-pairs, write 8 rows x 2x STG.128 ----
    const int y  = by + r;
    const int x0 = bx + xg;
    float* op = out + (((size_t)bb * F + f0) * H + y) * W + x0;
#pragma unroll
    for (int q = 0; q < 4; ++q) {
        float lo[8], hi[8];
#pragma unroll
        for (int p = 0; p < 8; ++p) unpack2(acc2[q][p], lo[p], hi[p]);
        *(float4*)(op + 0) = make_float4(lo[0], lo[1], lo[2], lo[3]);
        *(float4*)(op + 4) = make_float4(lo[4], lo[5], lo[6], lo[7]);
        op += (size_t)H * W;
        *(float4*)(op + 0) = make_float4(hi[0], hi[1], hi[2], hi[3]);
        *(float4*)(op + 4) = make_float4(hi[4], hi[5], hi[6], hi[7]);
        op += (size_t)H * W;
    }
}

extern "C" void kernel_launch(void* const* d_in, const int* in_sizes, int n_in,
                              void* d_out, int out_size)
{
    (void)in_sizes; (void)n_in; (void)out_size;
    const float* in = (const float*)d_in[0];   // dataset [32,64,112,112] f32
    const float* wt = (const float*)d_in[1];   // filters [128,64,3,3]    f32
    float* out = (float*)d_out;                // [32,128,112,112] f32

    dim3 grid(W / TX, H / TY, B);              // (7, 14, 32) = 3136 blocks
    conv3x3_kernel<<<grid, TPB>>>(in, wt, out);
}

// round 4
// speedup vs baseline: 2.6081x; 2.2101x over previous
#include <cuda_runtime.h>
#include <cstdint>

#define TPB 256

namespace {
constexpr int Cn = 64, Hn = 112, Wn = 112, Fn = 128;
constexpr int PIX    = Hn * Wn;        // 12544
constexpr int Ktot   = 576;            // 64 ch * 9 taps; k = c*9 + (dy*3+dx)
constexpr int KC     = 64;             // k per chunk
constexpr int NCHUNK = Ktot / KC;      // 9
constexpr int APAD   = 136;            // A pitch (words), k-major [KC][APAD]
constexpr int BPAD   = 68;             // B pitch (words), f-major [Fn][BPAD]
constexpr int SMEM_WORDS = KC * APAD + Fn * BPAD;     // 8704+8704
constexpr int SMEM_BYTES = SMEM_WORDS * 4;            // 69632
}

__device__ __forceinline__ uint32_t f2tf32(float x) {
    uint32_t r;
    asm("cvt.rna.tf32.f32 %0, %1;" : "=r"(r) : "f"(x));
    return r;
}

// D[m=128 pixels][n=128 filters] += A[m][k] * B[n][k], K=576 (implicit im2col)
__global__ __launch_bounds__(TPB, 2)
void conv_mma_kernel(const float* __restrict__ in, const float* __restrict__ wt,
                     float* __restrict__ out)
{
    extern __shared__ uint32_t smem[];
    uint32_t* sA = smem;                 // [KC][APAD]  (tf32 bits)
    uint32_t* sB = smem + KC * APAD;     // [Fn][BPAD]

    const int tid  = threadIdx.x;
    const int wid  = tid >> 5;
    const int lane = tid & 31;
    const int b    = blockIdx.y;
    const int p0   = blockIdx.x * 128;   // flattened pixel base (98 tiles exact)

    const int wm0 = (wid & 1) * 64;      // warp M origin
    const int wn0 = (wid >> 1) * 32;     // warp N origin

    // per-thread A-build coords (fixed pixel, two k-lanes)
    const int mA  = tid & 127;
    const int kA0 = tid >> 7;            // 0 or 1
    const int py  = (p0 + mA) / Wn;
    const int px  = (p0 + mA) % Wn;
    const float*  in_b = in + (size_t)b * Cn * PIX;
    const float4* wt4  = (const float4*)wt;   // [Fn][144]

    float acc[4][4][4];
#pragma unroll
    for (int mi = 0; mi < 4; ++mi)
#pragma unroll
        for (int ni = 0; ni < 4; ++ni)
#pragma unroll
            for (int c = 0; c < 4; ++c) acc[mi][ni][c] = 0.f;

#pragma unroll 1
    for (int ch = 0; ch < NCHUNK; ++ch) {
        const int k0 = ch * KC;
        __syncthreads();                 // previous chunk's compute finished

        // ---- build A chunk: [64 k][128 m], masked coalesced loads ----
#pragma unroll
        for (int i = 0; i < 32; ++i) {
            const int k  = kA0 + 2 * i;
            const int kg = k0 + k;
            const int c  = kg / 9;
            const int t  = kg - c * 9;
            const int dy = t / 3;
            const int dx = t - dy * 3;
            const int yy = py + dy - 1;
            const int xx = px + dx - 1;
            const bool v = ((unsigned)yy < (unsigned)Hn) &&
                           ((unsigned)xx < (unsigned)Wn);
            float val = v ? __ldg(in_b + (size_t)c * PIX + yy * Wn + xx) : 0.f;
            sA[k * APAD + mA] = f2tf32(val);
        }

        // ---- build B chunk: [128 f][64 k], contiguous float4 per filter ----
#pragma unroll
        for (int i = 0; i < 8; ++i) {
            const int idx = i * TPB + tid;
            const int f = idx >> 4;
            const int g = idx & 15;
            float4 v = __ldg(&wt4[f * 144 + (k0 >> 2) + g]);
            uint32_t* dst = sB + f * BPAD + g * 4;
            dst[0] = f2tf32(v.x); dst[1] = f2tf32(v.y);
            dst[2] = f2tf32(v.z); dst[3] = f2tf32(v.w);
        }
        __syncthreads();

        // ---- compute: 8 k-steps x 16 mma(m16n8k8) per warp ----
#pragma unroll
        for (int s = 0; s < 8; ++s) {
            uint32_t af[4][4], bf[4][2];
            const int ka = s * 8 + (lane & 3);
            const int ra = wm0 + (lane >> 2);
#pragma unroll
            for (int mi = 0; mi < 4; ++mi) {
                const uint32_t* pa = sA + ka * APAD + ra + mi * 16;
                af[mi][0] = pa[0];
                af[mi][1] = pa[8];
                af[mi][2] = pa[4 * APAD];
                af[mi][3] = pa[4 * APAD + 8];
            }
#pragma unroll
            for (int ni = 0; ni < 4; ++ni) {
                const uint32_t* pb =
                    sB + (wn0 + ni * 8 + (lane >> 2)) * BPAD + s * 8 + (lane & 3);
                bf[ni][0] = pb[0];
                bf[ni][1] = pb[4];
            }
#pragma unroll
            for (int mi = 0; mi < 4; ++mi)
#pragma unroll
                for (int ni = 0; ni < 4; ++ni)
                    asm volatile(
                        "mma.sync.aligned.m16n8k8.row.col.f32.tf32.tf32.f32 "
                        "{%0,%1,%2,%3}, {%4,%5,%6,%7}, {%8,%9}, {%0,%1,%2,%3};"
                        : "+f"(acc[mi][ni][0]), "+f"(acc[mi][ni][1]),
                          "+f"(acc[mi][ni][2]), "+f"(acc[mi][ni][3])
                        : "r"(af[mi][0]), "r"(af[mi][1]),
                          "r"(af[mi][2]), "r"(af[mi][3]),
                          "r"(bf[ni][0]), "r"(bf[ni][1]));
        }
    }

    // ---- epilogue: scatter accumulators to NCHW output ----
    float* out_b = out + (size_t)b * Fn * PIX + p0;
#pragma unroll
    for (int mi = 0; mi < 4; ++mi) {
        const int r0 = wm0 + mi * 16 + (lane >> 2);
#pragma unroll
        for (int ni = 0; ni < 4; ++ni) {
            const int n0 = wn0 + ni * 8 + (lane & 3) * 2;
            out_b[(size_t)n0 * PIX + r0]           = acc[mi][ni][0];
            out_b[(size_t)(n0 + 1) * PIX + r0]     = acc[mi][ni][1];
            out_b[(size_t)n0 * PIX + r0 + 8]       = acc[mi][ni][2];
            out_b[(size_t)(n0 + 1) * PIX + r0 + 8] = acc[mi][ni][3];
        }
    }
}

extern "C" void kernel_launch(void* const* d_in, const int* in_sizes, int n_in,
                              void* d_out, int out_size)
{
    (void)in_sizes; (void)n_in; (void)out_size;
    const float* in = (const float*)d_in[0];   // [32,64,112,112]
    const float* wt = (const float*)d_in[1];   // [128,64,3,3]
    float* out = (float*)d_out;                // [32,128,112,112]

    static bool attr_set = false;
    if (!attr_set) {
        cudaFuncSetAttribute(conv_mma_kernel,
                             cudaFuncAttributeMaxDynamicSharedMemorySize, SMEM_BYTES);
        attr_set = true;
    }
    dim3 grid(PIX / 128, 32);                  // (98, 32) = 3136 CTAs
    conv_mma_kernel<<<grid, TPB, SMEM_BYTES>>>(in, wt, out);
}

// round 5
// speedup vs baseline: 3.1153x; 1.1945x over previous
#include <cuda_runtime.h>
#include <cstdint>

#define TPB 256

namespace {
constexpr int Cn = 64, Hn = 112, Wn = 112, Fn = 128;
constexpr int PIX   = Hn * Wn;          // 12544
constexpr int PITCH = 136;              // smem row pitch (words), 136 % 32 == 8
constexpr int BUFW  = 32 * PITCH;       // words per buffer (K=32 chunk)
constexpr int NCH   = 18;               // 9 taps x 2 channel halves
constexpr int SMEM_BYTES = 6 * BUFW * 4;  // 3x A + 3x B = 104448 B
}

// pre-transposed, pre-converted (tf32 RNA) weights: [tap][c][f]
__device__ __align__(16) uint32_t g_wt[9 * 64 * 128];

__device__ __forceinline__ uint32_t f2tf32(float x) {
    uint32_t r;
    asm("cvt.rna.tf32.f32 %0, %1;" : "=r"(r) : "f"(x));
    return r;
}
__device__ __forceinline__ uint32_t smem_u32(const void* p) {
    uint32_t a;
    asm("{ .reg .u64 t; cvta.to.shared.u64 t, %1; cvt.u32.u64 %0, t; }" : "=r"(a) : "l"(p));
    return a;
}
__device__ __forceinline__ void cpa4(uint32_t dst, const void* src, int sz) {
    asm volatile("cp.async.ca.shared.global [%0], [%1], 4, %2;"
                 :: "r"(dst), "l"(src), "r"(sz));
}
__device__ __forceinline__ void cpa16(uint32_t dst, const void* src) {
    asm volatile("cp.async.cg.shared.global [%0], [%1], 16;"
                 :: "r"(dst), "l"(src));
}
#define CP_COMMIT() asm volatile("cp.async.commit_group;" ::: "memory")
#define CP_WAIT1()  asm volatile("cp.async.wait_group 1;"  ::: "memory")
#define CP_WAIT0()  asm volatile("cp.async.wait_group 0;"  ::: "memory")

// setup: g_wt[(tap*64 + c)*128 + f] = tf32(wt[f*576 + c*9 + tap])
__global__ void transpose_wt_kernel(const float* __restrict__ wt) {
    int i = blockIdx.x * 256 + threadIdx.x;
    if (i < 9 * 64 * 128) {
        int f = i & 127;
        int c = (i >> 7) & 63;
        int tap = i >> 13;
        g_wt[i] = f2tf32(wt[f * 576 + c * 9 + tap]);
    }
}

// D[m=128 pixels][n=128 filters] = sum_k A[m][k]*B[n][k], K = 576, tap-major k
__global__ void __launch_bounds__(TPB, 2)
conv_mma2_kernel(const float* __restrict__ in, float* __restrict__ out)
{
    extern __shared__ uint32_t smem[];
    const uint32_t sbase = smem_u32(smem);

    const int tid  = threadIdx.x;
    const int lane = tid & 31;
    const int wid  = tid >> 5;
    const int bb   = blockIdx.y;
    const int p0   = blockIdx.x * 128;

    const int wm0 = (wid & 1) * 64;
    const int wn0 = (wid >> 1) * 32;

    // copy-role: this thread stages 4 m-columns (m4*4..+3) x rows c = cgrp+8j
    const int m4   = tid & 31;
    const int cgrp = tid >> 5;

    // per-thread edge masks over its 4 m values (bit e -> m = m4*4+e)
    uint32_t mPX0 = 0, mPXW = 0, mPY0 = 0, mPYH = 0;
#pragma unroll
    for (int e = 0; e < 4; ++e) {
        int p  = p0 + m4 * 4 + e;
        int py = p / Wn;
        int px = p - py * Wn;
        if (px == 0)      mPX0 |= 1u << e;
        if (px == Wn - 1) mPXW |= 1u << e;
        if (py == 0)      mPY0 |= 1u << e;
        if (py == Hn - 1) mPYH |= 1u << e;
    }
    const float* in_b = in + (size_t)bb * Cn * PIX;

    float acc[4][4][4];
#pragma unroll
    for (int mi = 0; mi < 4; ++mi)
#pragma unroll
        for (int ni = 0; ni < 4; ++ni)
#pragma unroll
            for (int c = 0; c < 4; ++c) acc[mi][ni][c] = 0.f;

    // ---- chunk copy: stage A (zero-filled edges) + B into buffer ch%3 ----
    auto issue = [&](int ch) {
        const int buf   = ch % 3;
        const int tap   = ch >> 1;
        const int c0    = (ch & 1) * 32;
        const int dy    = tap / 3;
        const int dx    = tap - dy * 3;
        const int shift = (dy - 1) * Wn + dx - 1;
        const uint32_t bm = ((dx == 0) ? mPX0 : 0u) | ((dx == 2) ? mPXW : 0u) |
                            ((dy == 0) ? mPY0 : 0u) | ((dy == 2) ? mPYH : 0u);

        int pcl[4], szv[4];
#pragma unroll
        for (int e = 0; e < 4; ++e) {
            int p = p0 + m4 * 4 + e + shift;
            pcl[e] = min(max(p, 0), PIX - 1);
            szv[e] = ((bm >> e) & 1u) ? 0 : 4;
        }
        const uint32_t adst = sbase + (buf * BUFW + m4 * 4) * 4;
#pragma unroll
        for (int j = 0; j < 4; ++j) {
            const int c = cgrp + 8 * j;
            const float* srcb = in_b + (size_t)(c0 + c) * PIX;
            const uint32_t d = adst + c * (PITCH * 4);
#pragma unroll
            for (int e = 0; e < 4; ++e)
                cpa4(d + e * 4, srcb + pcl[e], szv[e]);
        }
        const uint32_t* wsrc = g_wt + ((size_t)tap * 64 + c0) * 128 + m4 * 4;
        const uint32_t bdst  = sbase + ((3 + buf) * BUFW + m4 * 4) * 4;
#pragma unroll
        for (int j = 0; j < 4; ++j) {
            const int c = cgrp + 8 * j;
            cpa16(bdst + c * (PITCH * 4), wsrc + c * 128);
        }
        CP_COMMIT();
    };

    // ---- 3-stage pipeline over 18 chunks ----
    issue(0);
    issue(1);
#pragma unroll 1
    for (int ch = 0; ch < NCH; ++ch) {
        if (ch + 1 < NCH) CP_WAIT1(); else CP_WAIT0();
        __syncthreads();
        if (ch + 2 < NCH) issue(ch + 2);

        // compute chunk ch: 4 k-steps x 16 mma(m16n8k8)
        const uint32_t aw = (ch % 3) * BUFW;
        const uint32_t bw = (3 + ch % 3) * BUFW;
#pragma unroll
        for (int s = 0; s < 4; ++s) {
            const int ka = s * 8 + (lane & 3);
            uint32_t af[4][4], bf[4][2];
            const uint32_t* pa = smem + aw + ka * PITCH + wm0 + (lane >> 2);
#pragma unroll
            for (int mi = 0; mi < 4; ++mi) {
                af[mi][0] = f2tf32(__uint_as_float(pa[mi * 16]));
                af[mi][1] = f2tf32(__uint_as_float(pa[mi * 16 + 8]));
                af[mi][2] = f2tf32(__uint_as_float(pa[4 * PITCH + mi * 16]));
                af[mi][3] = f2tf32(__uint_as_float(pa[4 * PITCH + mi * 16 + 8]));
            }
            const uint32_t* pb = smem + bw + ka * PITCH + wn0 + (lane >> 2);
#pragma unroll
            for (int ni = 0; ni < 4; ++ni) {
                bf[ni][0] = pb[ni * 8];
                bf[ni][1] = pb[4 * PITCH + ni * 8];
            }
#pragma unroll
            for (int mi = 0; mi < 4; ++mi)
#pragma unroll
                for (int ni = 0; ni < 4; ++ni)
                    asm volatile(
                        "mma.sync.aligned.m16n8k8.row.col.f32.tf32.tf32.f32 "
                        "{%0,%1,%2,%3}, {%4,%5,%6,%7}, {%8,%9}, {%0,%1,%2,%3};"
                        : "+f"(acc[mi][ni][0]), "+f"(acc[mi][ni][1]),
                          "+f"(acc[mi][ni][2]), "+f"(acc[mi][ni][3])
                        : "r"(af[mi][0]), "r"(af[mi][1]),
                          "r"(af[mi][2]), "r"(af[mi][3]),
                          "r"(bf[ni][0]), "r"(bf[ni][1]));
        }
    }

    // ---- epilogue: scatter to NCHW ----
    float* out_b = out + (size_t)bb * Fn * PIX + p0;
#pragma unroll
    for (int mi = 0; mi < 4; ++mi) {
        const int r0 = wm0 + mi * 16 + (lane >> 2);
#pragma unroll
        for (int ni = 0; ni < 4; ++ni) {
            const int n0 = wn0 + ni * 8 + (lane & 3) * 2;
            out_b[(size_t)n0 * PIX + r0]           = acc[mi][ni][0];
            out_b[(size_t)(n0 + 1) * PIX + r0]     = acc[mi][ni][1];
            out_b[(size_t)n0 * PIX + r0 + 8]       = acc[mi][ni][2];
            out_b[(size_t)(n0 + 1) * PIX + r0 + 8] = acc[mi][ni][3];
        }
    }
}

extern "C" void kernel_launch(void* const* d_in, const int* in_sizes, int n_in,
                              void* d_out, int out_size)
{
    (void)in_sizes; (void)n_in; (void)out_size;
    const float* in = (const float*)d_in[0];   // [32,64,112,112]
    const float* wt = (const float*)d_in[1];   // [128,64,3,3]
    float* out = (float*)d_out;                // [32,128,112,112]

    static bool attr_set = false;
    if (!attr_set) {
        cudaFuncSetAttribute(conv_mma2_kernel,
                             cudaFuncAttributeMaxDynamicSharedMemorySize, SMEM_BYTES);
        attr_set = true;
    }
    transpose_wt_kernel<<<288, 256>>>(wt);
    dim3 grid(PIX / 128, 32);                  // (98, 32)
    conv_mma2_kernel<<<grid, TPB, SMEM_BYTES>>>(in, out);
}

// round 7
// speedup vs baseline: 3.6458x; 1.1703x over previous
#include <cuda_runtime.h>
#include <cstdint>

#define TPB 256

namespace {
constexpr int Cn = 64, Hn = 112, Wn = 112, Fn = 128;
constexpr int PIX   = Hn * Wn;           // 12544
constexpr int CPW   = 484;               // s_in words per channel (4 rows x 120 + pad), 484%32=4
constexpr int ROWW  = 120;               // padded row width (words)
constexpr int SIN_W = 32 * CPW;          // 15488 words
constexpr int BPITCH = 132;              // B pitch (words), 132%32=4
constexpr int BW    = 32 * BPITCH;       // 4224 words per B buffer
constexpr int SMEM_WORDS = SIN_W + 2 * BW;   // 23936
constexpr int SMEM_BYTES = SMEM_WORDS * 4;   // 95744
}

// pre-transposed, pre-converted (tf32 RNA) weights: [tap][c][f]
__device__ __align__(16) uint32_t g_wt[9 * 64 * 128];

__device__ __forceinline__ uint32_t f2tf32(float x) {
    uint32_t r;
    asm("cvt.rna.tf32.f32 %0, %1;" : "=r"(r) : "f"(x));
    return r;
}
__device__ __forceinline__ uint32_t smem_u32(const void* p) {
    uint32_t a;
    asm("{ .reg .u64 t; cvta.to.shared.u64 t, %1; cvt.u32.u64 %0, t; }" : "=r"(a) : "l"(p));
    return a;
}
__device__ __forceinline__ void cpa16z(uint32_t dst, const void* src, int sz) {
    asm volatile("cp.async.cg.shared.global [%0], [%1], 16, %2;"
                 :: "r"(dst), "l"(src), "r"(sz));
}
__device__ __forceinline__ void cpa16(uint32_t dst, const void* src) {
    asm volatile("cp.async.cg.shared.global [%0], [%1], 16;"
                 :: "r"(dst), "l"(src));
}
#define CP_COMMIT() asm volatile("cp.async.commit_group;" ::: "memory")
#define CP_WAIT0()  asm volatile("cp.async.wait_group 0;"  ::: "memory")

__global__ void transpose_wt_kernel(const float* __restrict__ wt) {
    int i = blockIdx.x * 256 + threadIdx.x;
    if (i < 9 * 64 * 128) {
        int f = i & 127;
        int c = (i >> 7) & 63;
        int tap = i >> 13;
        g_wt[i] = f2tf32(wt[f * 576 + c * 9 + tap]);
    }
}

// D[m=128 pixels][n=128 filters] = sum_{tap,c} A * B ; input staged once per c-half
__global__ void __launch_bounds__(TPB, 2)
conv_mma3_kernel(const float* __restrict__ in, float* __restrict__ out)
{
    extern __shared__ uint32_t smem[];
    const uint32_t sbase = smem_u32(smem);

    const int tid  = threadIdx.x;
    const int lane = tid & 31;
    const int wid  = tid >> 5;
    const int bb   = blockIdx.y;
    const int p0   = blockIdx.x * 128;
    const int py0  = p0 / Wn;
    const int px0  = p0 - py0 * Wn;     // multiple of 16, <= 96

    const int wm0 = (wid & 1) * 64;
    const int wn0 = (wid >> 1) * 32;
    const float* in_b = in + (size_t)bb * Cn * PIX;

    // per-thread A fragment offsets: 8 m-values -> word offset (r*120 + x + 3)
    int om[8];
#pragma unroll
    for (int q = 0; q < 8; ++q) {
        int m = wm0 + (lane >> 2) + (q >> 1) * 16 + (q & 1) * 8;
        int x = px0 + m;
        int r = 0;
        if (x >= Wn) { x -= Wn; r = 1; }
        om[q] = r * ROWW + x + 3;
    }

    // zero the x-borders (cols 3 and 116) once; never overwritten by copies
    {
        int c = tid >> 3, ry = (tid >> 1) & 3, side = tid & 1;
        smem[c * CPW + ry * ROWW + (side ? 116 : 3)] = 0;
    }

    float acc[4][4][4];
#pragma unroll
    for (int mi = 0; mi < 4; ++mi)
#pragma unroll
        for (int ni = 0; ni < 4; ++ni)
#pragma unroll
            for (int c = 0; c < 4; ++c) acc[mi][ni][c] = 0.f;

    auto stage_sin = [&](int c0) {
#pragma unroll
        for (int i = 0; i < 14; ++i) {          // 3584 cpa16 / 256 threads
            int e   = i * 256 + tid;
            int x16 = e % 28;
            int cr  = e / 28;                    // 0..127
            int ry  = cr & 3;
            int c   = cr >> 2;
            int y   = py0 - 1 + ry;
            int yc  = min(max(y, 0), Hn - 1);
            const float* src = in_b + (size_t)(c0 + c) * PIX + yc * Wn + x16 * 4;
            int sz = ((unsigned)y < (unsigned)Hn) ? 16 : 0;
            cpa16z(sbase + (c * CPW + ry * ROWW + 4 + x16 * 4) * 4, src, sz);
        }
    };
    auto stage_B = [&](int tap, int c0, int buf) {
        const uint32_t* wb = g_wt + (((size_t)tap * 64 + c0) << 7);
#pragma unroll
        for (int i = 0; i < 4; ++i) {            // 1024 cpa16 / 256 threads
            int e = i * 256 + tid;
            int f16 = e & 31, c = e >> 5;
            cpa16(sbase + (SIN_W + buf * BW + c * BPITCH + f16 * 4) * 4,
                  wb + c * 128 + f16 * 4);
        }
    };

#pragma unroll 1
    for (int ch = 0; ch < 2; ++ch) {
        const int c0 = ch * 32;
        __syncthreads();                  // prior readers of s_in done
        stage_sin(c0);
        stage_B(0, c0, 0);
        CP_COMMIT();

#pragma unroll 1
        for (int tap = 0; tap < 9; ++tap) {
            CP_WAIT0();
            __syncthreads();
            if (tap < 8) { stage_B(tap + 1, c0, (tap + 1) & 1); CP_COMMIT(); }

            const int dy = tap / 3, dx = tap - dy * 3;
            const int dyx = dy * ROWW + dx;
            const uint32_t* sB = smem + SIN_W + (tap & 1) * BW;

            // 4 k-steps of K=8 over this 32-channel half (cb in [0,31])
#pragma unroll
            for (int s = 0; s < 4; ++s) {
                const int cb = s * 8 + (lane & 3);
                const uint32_t* pa  = smem + cb * CPW + dyx;
                const uint32_t* pa4 = pa + 4 * CPW;
                uint32_t af[4][4], bf[4][2];
#pragma unroll
                for (int mi = 0; mi < 4; ++mi) {
                    af[mi][0] = pa [om[2 * mi]];
                    af[mi][1] = pa [om[2 * mi + 1]];
                    af[mi][2] = pa4[om[2 * mi]];
                    af[mi][3] = pa4[om[2 * mi + 1]];
                }
                const uint32_t* pb = sB + cb * BPITCH + wn0 + (lane >> 2);
#pragma unroll
                for (int ni = 0; ni < 4; ++ni) {
                    bf[ni][0] = pb[ni * 8];
                    bf[ni][1] = pb[4 * BPITCH + ni * 8];
                }
#pragma unroll
                for (int mi = 0; mi < 4; ++mi)
#pragma unroll
                    for (int ni = 0; ni < 4; ++ni)
                        asm volatile(
                            "mma.sync.aligned.m16n8k8.row.col.f32.tf32.tf32.f32 "
                            "{%0,%1,%2,%3}, {%4,%5,%6,%7}, {%8,%9}, {%0,%1,%2,%3};"
                            : "+f"(acc[mi][ni][0]), "+f"(acc[mi][ni][1]),
                              "+f"(acc[mi][ni][2]), "+f"(acc[mi][ni][3])
                            : "r"(af[mi][0]), "r"(af[mi][1]),
                              "r"(af[mi][2]), "r"(af[mi][3]),
                              "r"(bf[ni][0]), "r"(bf[ni][1]));
            }
        }
    }

    // ---- epilogue: scatter to NCHW ----
    float* out_b = out + (size_t)bb * Fn * PIX + p0;
#pragma unroll
    for (int mi = 0; mi < 4; ++mi) {
        const int r0 = wm0 + mi * 16 + (lane >> 2);
#pragma unroll
        for (int ni = 0; ni < 4; ++ni) {
            const int n0 = wn0 + ni * 8 + (lane & 3) * 2;
            out_b[(size_t)n0 * PIX + r0]           = acc[mi][ni][0];
            out_b[(size_t)(n0 + 1) * PIX + r0]     = acc[mi][ni][1];
            out_b[(size_t)n0 * PIX + r0 + 8]       = acc[mi][ni][2];
            out_b[(size_t)(n0 + 1) * PIX + r0 + 8] = acc[mi][ni][3];
        }
    }
}

extern "C" void kernel_launch(void* const* d_in, const int* in_sizes, int n_in,
                              void* d_out, int out_size)
{
    (void)in_sizes; (void)n_in; (void)out_size;
    const float* in = (const float*)d_in[0];   // [32,64,112,112]
    const float* wt = (const float*)d_in[1];   // [128,64,3,3]
    float* out = (float*)d_out;                // [32,128,112,112]

    static bool attr_set = false;
    if (!attr_set) {
        cudaFuncSetAttribute(conv_mma3_kernel,
                             cudaFuncAttributeMaxDynamicSharedMemorySize, SMEM_BYTES);
        attr_set = true;
    }
    transpose_wt_kernel<<<288, 256>>>(wt);
    dim3 grid(PIX / 128, 32);                  // (98, 32)
    conv_mma3_kernel<<<grid, TPB, SMEM_BYTES>>>(in, out);
}

// round 8
// speedup vs baseline: 4.0493x; 1.1107x over previous
#include <cuda_runtime.h>
#include <cstdint>

#define TPB 128

namespace {
constexpr int Cn = 64, Hn = 112, Wn = 112, Fn = 128;
constexpr int PIX   = Hn * Wn;           // 12544
constexpr int CPW   = 484;               // s_in words per channel (4 rows x 120 + pad)
constexpr int ROWW  = 120;               // padded row width (words)
constexpr int SIN_W = 32 * CPW;          // 15488 words
constexpr int BPITCH = 132;              // B pitch (words)
constexpr int BW    = 32 * BPITCH;       // 4224 words per B buffer
constexpr int SMEM_WORDS = SIN_W + 2 * BW;   // 23936
constexpr int SMEM_BYTES = SMEM_WORDS * 4;   // 95744
}

// pre-transposed, pre-converted (tf32 RNA) weights: [tap][c][f]
__device__ __align__(16) uint32_t g_wt[9 * 64 * 128];

__device__ __forceinline__ uint32_t f2tf32(float x) {
    uint32_t r;
    asm("cvt.rna.tf32.f32 %0, %1;" : "=r"(r) : "f"(x));
    return r;
}
__device__ __forceinline__ uint32_t smem_u32(const void* p) {
    uint32_t a;
    asm("{ .reg .u64 t; cvta.to.shared.u64 t, %1; cvt.u32.u64 %0, t; }" : "=r"(a) : "l"(p));
    return a;
}
__device__ __forceinline__ void cpa16z(uint32_t dst, const void* src, int sz) {
    asm volatile("cp.async.cg.shared.global [%0], [%1], 16, %2;"
                 :: "r"(dst), "l"(src), "r"(sz));
}
__device__ __forceinline__ void cpa16(uint32_t dst, const void* src) {
    asm volatile("cp.async.cg.shared.global [%0], [%1], 16;"
                 :: "r"(dst), "l"(src));
}
#define CP_COMMIT() asm volatile("cp.async.commit_group;" ::: "memory")
#define CP_WAIT0()  asm volatile("cp.async.wait_group 0;"  ::: "memory")

__global__ void transpose_wt_kernel(const float* __restrict__ wt) {
    int i = blockIdx.x * 256 + threadIdx.x;
    if (i < 9 * 64 * 128) {
        int f = i & 127;
        int c = (i >> 7) & 63;
        int tap = i >> 13;
        g_wt[i] = f2tf32(wt[f * 576 + c * 9 + tap]);
    }
}

// D[m=128 pixels][n=128 filters]; 4 warps, warp tile 64x64 (2m x 2n grid)
__global__ void __launch_bounds__(TPB, 2)
conv_mma4_kernel(const float* __restrict__ in, float* __restrict__ out)
{
    extern __shared__ uint32_t smem[];
    const uint32_t sbase = smem_u32(smem);

    const int tid  = threadIdx.x;
    const int lane = tid & 31;
    const int wid  = tid >> 5;          // 0..3
    const int bb   = blockIdx.y;
    const int p0   = blockIdx.x * 128;
    const int py0  = p0 / Wn;
    const int px0  = p0 - py0 * Wn;     // multiple of 16, <= 96

    const int wm0 = (wid & 1) * 64;
    const int wn0 = (wid >> 1) * 64;
    const float* in_b = in + (size_t)bb * Cn * PIX;

    // per-thread A fragment offsets: 8 m-values -> word offset (r*120 + x + 3)
    int om[8];
#pragma unroll
    for (int q = 0; q < 8; ++q) {
        int m = wm0 + (lane >> 2) + (q >> 1) * 16 + (q & 1) * 8;
        int x = px0 + m;
        int r = 0;
        if (x >= Wn) { x -= Wn; r = 1; }
        om[q] = r * ROWW + x + 3;
    }

    // zero the x-borders (cols 3 and 116) once; never overwritten by copies
#pragma unroll
    for (int j = 0; j < 2; ++j) {
        int e = j * TPB + tid;            // 0..255
        int c = e >> 3, ry = (e >> 1) & 3, side = e & 1;
        smem[c * CPW + ry * ROWW + (side ? 116 : 3)] = 0;
    }

    float acc[4][8][4];
#pragma unroll
    for (int mi = 0; mi < 4; ++mi)
#pragma unroll
        for (int ni = 0; ni < 8; ++ni)
#pragma unroll
            for (int c = 0; c < 4; ++c) acc[mi][ni][c] = 0.f;

    auto stage_sin = [&](int c0) {
#pragma unroll
        for (int i = 0; i < 28; ++i) {          // 3584 cpa16 / 128 threads
            int e   = i * TPB + tid;
            int x16 = e % 28;
            int cr  = e / 28;                    // 0..127
            int ry  = cr & 3;
            int c   = cr >> 2;
            int y   = py0 - 1 + ry;
            int yc  = min(max(y, 0), Hn - 1);
            const float* src = in_b + (size_t)(c0 + c) * PIX + yc * Wn + x16 * 4;
            int sz = ((unsigned)y < (unsigned)Hn) ? 16 : 0;
            cpa16z(sbase + (c * CPW + ry * ROWW + 4 + x16 * 4) * 4, src, sz);
        }
    };
    auto stage_B = [&](int tap, int c0, int buf) {
        const uint32_t* wb = g_wt + (((size_t)tap * 64 + c0) << 7);
#pragma unroll
        for (int i = 0; i < 8; ++i) {            // 1024 cpa16 / 128 threads
            int e = i * TPB + tid;
            int f16 = e & 31, c = e >> 5;
            cpa16(sbase + (SIN_W + buf * BW + c * BPITCH + f16 * 4) * 4,
                  wb + c * 128 + f16 * 4);
        }
    };

#pragma unroll 1
    for (int ch = 0; ch < 2; ++ch) {
        const int c0 = ch * 32;
        __syncthreads();                  // prior readers of s_in done
        stage_sin(c0);
        stage_B(0, c0, 0);
        CP_COMMIT();

#pragma unroll 1
        for (int tap = 0; tap < 9; ++tap) {
            CP_WAIT0();
            __syncthreads();
            if (tap < 8) { stage_B(tap + 1, c0, (tap + 1) & 1); CP_COMMIT(); }

            const int dy = tap / 3, dx = tap - dy * 3;
            const int dyx = dy * ROWW + dx;
            const uint32_t* sB = smem + SIN_W + (tap & 1) * BW;

            // 4 k-steps of K=8 over this 32-channel half
#pragma unroll
            for (int s = 0; s < 4; ++s) {
                const int cb = s * 8 + (lane & 3);
                const uint32_t* pa  = smem + cb * CPW + dyx;
                const uint32_t* pa4 = pa + 4 * CPW;
                uint32_t af[4][4], bf[8][2];
#pragma unroll
                for (int mi = 0; mi < 4; ++mi) {
                    af[mi][0] = pa [om[2 * mi]];
                    af[mi][1] = pa [om[2 * mi + 1]];
                    af[mi][2] = pa4[om[2 * mi]];
                    af[mi][3] = pa4[om[2 * mi + 1]];
                }
                const uint32_t* pb = sB + cb * BPITCH + wn0 + (lane >> 2);
#pragma unroll
                for (int ni = 0; ni < 8; ++ni) {
                    bf[ni][0] = pb[ni * 8];
                    bf[ni][1] = pb[4 * BPITCH + ni * 8];
                }
#pragma unroll
                for (int mi = 0; mi < 4; ++mi)
#pragma unroll
                    for (int ni = 0; ni < 8; ++ni)
                        asm volatile(
                            "mma.sync.aligned.m16n8k8.row.col.f32.tf32.tf32.f32 "
                            "{%0,%1,%2,%3}, {%4,%5,%6,%7}, {%8,%9}, {%0,%1,%2,%3};"
                            : "+f"(acc[mi][ni][0]), "+f"(acc[mi][ni][1]),
                              "+f"(acc[mi][ni][2]), "+f"(acc[mi][ni][3])
                            : "r"(af[mi][0]), "r"(af[mi][1]),
                              "r"(af[mi][2]), "r"(af[mi][3]),
                              "r"(bf[ni][0]), "r"(bf[ni][1]));
            }
        }
    }

    // ---- epilogue: scatter to NCHW ----
    float* out_b = out + (size_t)bb * Fn * PIX + p0;
#pragma unroll
    for (int mi = 0; mi < 4; ++mi) {
        const int r0 = wm0 + mi * 16 + (lane >> 2);
#pragma unroll
        for (int ni = 0; ni < 8; ++ni) {
            const int n0 = wn0 + ni * 8 + (lane & 3) * 2;
            out_b[(size_t)n0 * PIX + r0]           = acc[mi][ni][0];
            out_b[(size_t)(n0 + 1) * PIX + r0]     = acc[mi][ni][1];
            out_b[(size_t)n0 * PIX + r0 + 8]       = acc[mi][ni][2];
            out_b[(size_t)(n0 + 1) * PIX + r0 + 8] = acc[mi][ni][3];
        }
    }
}

extern "C" void kernel_launch(void* const* d_in, const int* in_sizes, int n_in,
                              void* d_out, int out_size)
{
    (void)in_sizes; (void)n_in; (void)out_size;
    const float* in = (const float*)d_in[0];   // [32,64,112,112]
    const float* wt = (const float*)d_in[1];   // [128,64,3,3]
    float* out = (float*)d_out;                // [32,128,112,112]

    static bool attr_set = false;
    if (!attr_set) {
        cudaFuncSetAttribute(conv_mma4_kernel,
                             cudaFuncAttributeMaxDynamicSharedMemorySize, SMEM_BYTES);
        attr_set = true;
    }
    transpose_wt_kernel<<<288, 256>>>(wt);
    dim3 grid(PIX / 128, 32);                  // (98, 32)
    conv_mma4_kernel<<<grid, TPB, SMEM_BYTES>>>(in, out);
}

// round 9
// speedup vs baseline: 4.4367x; 1.0957x over previous
#include <cuda_runtime.h>
#include <cstdint>

#define TPB 128

namespace {
constexpr int Cn = 64, Hn = 112, Wn = 112, Fn = 128;
constexpr int PIX   = Hn * Wn;           // 12544
constexpr int CPW   = 484;               // s_in words per channel (4 rows x 120 + pad)
constexpr int ROWW  = 120;               // padded row width (words)
constexpr int SIN_W = 32 * CPW;          // 15488 words
constexpr int BPK   = 5120;              // packed-B words per (tap, c-half): 4s*2wn*32lane*20
constexpr int SMEM_WORDS = SIN_W + 2 * BPK;  // 25728
constexpr int SMEM_BYTES = SMEM_WORDS * 4;   // 102912
}

// fragment-packed tf32 weights: [tap][half][s][wnIdx][lane][20] (16 used + 4 pad)
__device__ __align__(16) uint32_t g_wt[9 * 2 * BPK];

__device__ __forceinline__ uint32_t f2tf32(float x) {
    uint32_t r;
    asm("cvt.rna.tf32.f32 %0, %1;" : "=r"(r) : "f"(x));
    return r;
}
__device__ __forceinline__ uint32_t smem_u32(const void* p) {
    uint32_t a;
    asm("{ .reg .u64 t; cvta.to.shared.u64 t, %1; cvt.u32.u64 %0, t; }" : "=r"(a) : "l"(p));
    return a;
}
__device__ __forceinline__ void cpa16z(uint32_t dst, const void* src, int sz) {
    asm volatile("cp.async.cg.shared.global [%0], [%1], 16, %2;"
                 :: "r"(dst), "l"(src), "r"(sz));
}
__device__ __forceinline__ void cpa16(uint32_t dst, const void* src) {
    asm volatile("cp.async.cg.shared.global [%0], [%1], 16;"
                 :: "r"(dst), "l"(src));
}
#define CP_COMMIT() asm volatile("cp.async.commit_group;" ::: "memory")
#define CP_WAIT0()  asm volatile("cp.async.wait_group 0;"  ::: "memory")

// build fragment-packed B: word i -> (tap, half, s, wnIdx, lane, w)
__global__ void pack_wt_kernel(const float* __restrict__ wt) {
    int i = blockIdx.x * 256 + threadIdx.x;
    if (i >= 9 * 2 * BPK) return;
    int w     = i % 20;
    int j     = i / 20;
    int lane  = j % 32;
    int t     = j / 32;
    int wnIdx = t % 2;
    int t2    = t / 2;
    int s     = t2 % 4;
    int t3    = t2 / 4;
    int half  = t3 % 2;
    int tap   = t3 / 2;
    uint32_t val = 0;
    if (w < 16) {
        int kk = w & 1;
        int ni = w >> 1;
        int c  = half * 32 + s * 8 + (lane & 3) + kk * 4;
        int f  = wnIdx * 64 + ni * 8 + (lane >> 2);
        val = f2tf32(wt[f * 576 + c * 9 + tap]);
    }
    g_wt[i] = val;
}

// D[m=128 pixels][n=128 filters]; 4 warps, warp tile 64x64 (2m x 2n grid)
__global__ void __launch_bounds__(TPB, 2)
conv_mma5_kernel(const float* __restrict__ in, float* __restrict__ out)
{
    extern __shared__ uint32_t smem[];
    const uint32_t sbase = smem_u32(smem);

    const int tid  = threadIdx.x;
    const int lane = tid & 31;
    const int wid  = tid >> 5;          // 0..3
    const int wnIdx = wid >> 1;         // 0 or 1
    const int bb   = blockIdx.y;
    const int p0   = blockIdx.x * 128;
    const int py0  = p0 / Wn;
    const int px0  = p0 - py0 * Wn;     // multiple of 16, <= 96

    const int wm0 = (wid & 1) * 64;
    const float* in_b = in + (size_t)bb * Cn * PIX;

    // per-thread A fragment offsets: 8 m-values -> word offset (r*120 + x + 3)
    int om[8];
#pragma unroll
    for (int q = 0; q < 8; ++q) {
        int m = wm0 + (lane >> 2) + (q >> 1) * 16 + (q & 1) * 8;
        int x = px0 + m;
        int r = 0;
        if (x >= Wn) { x -= Wn; r = 1; }
        om[q] = r * ROWW + x + 3;
    }

    // zero the x-borders (cols 3 and 116) once; never overwritten by copies
#pragma unroll
    for (int j = 0; j < 2; ++j) {
        int e = j * TPB + tid;            // 0..255
        int c = e >> 3, ry = (e >> 1) & 3, side = e & 1;
        smem[c * CPW + ry * ROWW + (side ? 116 : 3)] = 0;
    }

    float acc[4][8][4];
#pragma unroll
    for (int mi = 0; mi < 4; ++mi)
#pragma unroll
        for (int ni = 0; ni < 8; ++ni)
#pragma unroll
            for (int c = 0; c < 4; ++c) acc[mi][ni][c] = 0.f;

    auto stage_sin = [&](int c0) {
#pragma unroll
        for (int i = 0; i < 28; ++i) {          // 3584 cpa16 / 128 threads
            int e   = i * TPB + tid;
            int x16 = e % 28;
            int cr  = e / 28;                    // 0..127
            int ry  = cr & 3;
            int c   = cr >> 2;
            int y   = py0 - 1 + ry;
            int yc  = min(max(y, 0), Hn - 1);
            const float* src = in_b + (size_t)(c0 + c) * PIX + yc * Wn + x16 * 4;
            int sz = ((unsigned)y < (unsigned)Hn) ? 16 : 0;
            cpa16z(sbase + (c * CPW + ry * ROWW + 4 + x16 * 4) * 4, src, sz);
        }
    };
    auto stage_B = [&](int tap, int half, int buf) {
        const uint32_t* wb = g_wt + (size_t)(tap * 2 + half) * BPK;
#pragma unroll
        for (int i = 0; i < 10; ++i) {           // 1280 cpa16 / 128 threads
            int e = i * TPB + tid;
            cpa16(sbase + (SIN_W + buf * BPK + e * 4) * 4, wb + e * 4);
        }
    };

#pragma unroll 1
    for (int half = 0; half < 2; ++half) {
        const int c0 = half * 32;
        __syncthreads();                  // prior readers of s_in done
        stage_sin(c0);
        stage_B(0, half, 0);
        CP_COMMIT();

#pragma unroll 1
        for (int tap = 0; tap < 9; ++tap) {
            CP_WAIT0();
            __syncthreads();
            if (tap < 8) { stage_B(tap + 1, half, (tap + 1) & 1); CP_COMMIT(); }

            const int dy = tap / 3, dx = tap - dy * 3;
            const int dyx = dy * ROWW + dx;
            const uint32_t* sB = smem + SIN_W + (tap & 1) * BPK;

            // 4 k-steps of K=8 over this 32-channel half
#pragma unroll
            for (int s = 0; s < 4; ++s) {
                const int cb = s * 8 + (lane & 3);
                const uint32_t* pa  = smem + cb * CPW + dyx;
                const uint32_t* pa4 = pa + 4 * CPW;
                uint32_t af[4][4];
#pragma unroll
                for (int mi = 0; mi < 4; ++mi) {
                    af[mi][0] = pa [om[2 * mi]];
                    af[mi][1] = pa [om[2 * mi + 1]];
                    af[mi][2] = pa4[om[2 * mi]];
                    af[mi][3] = pa4[om[2 * mi + 1]];
                }
                // packed B fragment: 4x LDS.128, conflict-free (20-word stride)
                const uint32_t* pb = sB + ((s * 2 + wnIdx) * 32 + lane) * 20;
                uint4 b0 = *(const uint4*)(pb + 0);
                uint4 b1 = *(const uint4*)(pb + 4);
                uint4 b2 = *(const uint4*)(pb + 8);
                uint4 b3 = *(const uint4*)(pb + 12);
                uint32_t barr[16] = {b0.x, b0.y, b0.z, b0.w, b1.x, b1.y, b1.z, b1.w,
                                     b2.x, b2.y, b2.z, b2.w, b3.x, b3.y, b3.z, b3.w};
#pragma unroll
                for (int mi = 0; mi < 4; ++mi)
#pragma unroll
                    for (int ni = 0; ni < 8; ++ni)
                        asm volatile(
                            "mma.sync.aligned.m16n8k8.row.col.f32.tf32.tf32.f32 "
                            "{%0,%1,%2,%3}, {%4,%5,%6,%7}, {%8,%9}, {%0,%1,%2,%3};"
                            : "+f"(acc[mi][ni][0]), "+f"(acc[mi][ni][1]),
                              "+f"(acc[mi][ni][2]), "+f"(acc[mi][ni][3])
                            : "r"(af[mi][0]), "r"(af[mi][1]),
                              "r"(af[mi][2]), "r"(af[mi][3]),
                              "r"(barr[2 * ni]), "r"(barr[2 * ni + 1]));
            }
        }
    }

    // ---- coalesced epilogue: acc -> smem transpose -> 128B-contiguous STG ----
    float* sf = (float*)smem;            // s_out[m][n'] pitch 68 (reuses s_in)
    float* out_b = out + (size_t)bb * Fn * PIX + p0;
#pragma unroll 1
    for (int pass = 0; pass < 2; ++pass) {
        __syncthreads();                 // smem free / previous pass consumed
        if (wnIdx == pass) {
#pragma unroll
            for (int mi = 0; mi < 4; ++mi) {
                int r0 = wm0 + mi * 16 + (lane >> 2);
#pragma unroll
                for (int ni = 0; ni < 8; ++ni) {
                    int nn = ni * 8 + (lane & 3) * 2;
                    *(float2*)&sf[r0 * 68 + nn] =
                        make_float2(acc[mi][ni][0], acc[mi][ni][1]);
                    *(float2*)&sf[(r0 + 8) * 68 + nn] =
                        make_float2(acc[mi][ni][2], acc[mi][ni][3]);
                }
            }
        }
        __syncthreads();
        // thread tid owns pixel m=tid; 16x LDS.128 (conflict-free), 64 coalesced STG
#pragma unroll
        for (int jj = 0; jj < 16; ++jj) {
            float4 v = *(const float4*)&sf[tid * 68 + jj * 4];
            float* dst = out_b + (size_t)(pass * 64 + jj * 4) * PIX + tid;
            dst[0]            = v.x;
            dst[(size_t)PIX]     = v.y;
            dst[(size_t)2 * PIX] = v.z;
            dst[(size_t)3 * PIX] = v.w;
        }
    }
}

extern "C" void kernel_launch(void* const* d_in, const int* in_sizes, int n_in,
                              void* d_out, int out_size)
{
    (void)in_sizes; (void)n_in; (void)out_size;
    const float* in = (const float*)d_in[0];   // [32,64,112,112]
    const float* wt = (const float*)d_in[1];   // [128,64,3,3]
    float* out = (float*)d_out;                // [32,128,112,112]

    static bool attr_set = false;
    if (!attr_set) {
        cudaFuncSetAttribute(conv_mma5_kernel,
                             cudaFuncAttributeMaxDynamicSharedMemorySize, SMEM_BYTES);
        attr_set = true;
    }
    pack_wt_kernel<<<(9 * 2 * BPK + 255) / 256, 256>>>(wt);
    dim3 grid(PIX / 128, 32);                  // (98, 32)
    conv_mma5_kernel<<<grid, TPB, SMEM_BYTES>>>(in, out);
}